// round 13
// baseline (speedup 1.0000x reference)
#include <cuda_runtime.h>
#include <cuda_fp16.h>
#include <cstdint>

#define T_STEPS 12
#define BATCH   64
#define NODE    207
#define HID     16
#define HDIM    6624          // NODE*HID*2
#define IN_DIM  16560         // NODE*HID*5
#define X_DIM   3312          // NODE*HID
#define WSTRIDE 6656          // h staging floats (padded)
#define NB      138           // persistent grid: 138 blocks * 48 rows
#define ROWS_PB 48
#define CSM4    256           // fp32 f4 cached per row (elems [0,1024))
#define SELEMS  5632          // streamed elems per row (cols [1024,6656), zero-padded)
#define SGROUPS 704           // 8-elem groups per row
#define SITERS  22            // SGROUPS / 32
// smem: h (WSTRIDE floats) + fp32 cache (48 rows * 256 f4)
#define SMEM_BYTES (WSTRIDE * 4 + ROWS_PB * CSM4 * 16)   // 223232 B, 1 CTA/SM

// Scratch (device globals: allocation-free rule)
__device__ float    g_hz[BATCH * HDIM];
__device__ float    g_inpT[IN_DIM * BATCH];
__device__ float    g_pre[BATCH * HDIM];
__device__ __half   g_whi[(size_t)HDIM * SELEMS];   // fp16 hi, streamed (74.6 MB)
__device__ int8_t   g_wlo[(size_t)HDIM * SELEMS];   // int8 residual (37.3 MB)
__device__ float    g_wsc[HDIM];                    // per-row residual scale
__device__ unsigned g_bar[2];                       // [0]=count (monotone), [1]=phase

// ---------------------------------------------------------------------------
// Kernel H: per row, cols [1024,6656): hi = fp16(w), lo8 = round((w-hi)/s),
// s = rowmax|w-hi| / 127. Cols [0,1024) stay fp32 (read by kC from Whh).
// ---------------------------------------------------------------------------
__global__ __launch_bounds__(256) void kH(const float* __restrict__ W)
{
    const int o = blockIdx.x;
    const int tid = threadIdx.x;
    __shared__ float smax[256];

    float m = 0.f;
    for (int i = tid; i < SELEMS; i += 256) {
        const int col = 1024 + i;
        const float w = (col < HDIM) ? W[(size_t)o * HDIM + col] : 0.f;
        const __half hi = __float2half(w);
        g_whi[(size_t)o * SELEMS + i] = hi;
        const float r = w - __half2float(hi);
        m = fmaxf(m, fabsf(r));
    }
    smax[tid] = m;
    __syncthreads();
    for (int s = 128; s; s >>= 1) {
        if (tid < s) smax[tid] = fmaxf(smax[tid], smax[tid + s]);
        __syncthreads();
    }
    const float mx = smax[0];
    const float sc = (mx > 0.f) ? (mx / 127.f) : 1.f;
    if (tid == 0) g_wsc[o] = sc;
    const float inv = 1.f / sc;

    for (int i = tid; i < SELEMS; i += 256) {
        const int col = 1024 + i;
        const float w = (col < HDIM) ? W[(size_t)o * HDIM + col] : 0.f;
        const float r = w - __half2float(__float2half(w));
        float q = rintf(r * inv);
        q = fminf(fmaxf(q, -127.f), 127.f);
        g_wlo[(size_t)o * SELEMS + i] = (int8_t)(int)q;
    }
}

// ---------------------------------------------------------------------------
// Kernel A: build inpT[:, b] directly (transposed layout).
// ---------------------------------------------------------------------------
__global__ __launch_bounds__(256) void kA(
    const float* __restrict__ hz, const float* __restrict__ sv_t,
    const float* __restrict__ Wf, const float* __restrict__ bf,
    const float* __restrict__ Wg, const float* __restrict__ bg,
    const float* __restrict__ conv_w, float* __restrict__ inpT)
{
    const int blk = blockIdx.x;
    const int b = blk / NODE;
    const int n = blk % NODE;
    const int tid = threadIdx.x;

    __shared__ float sh[HID], sz[HID], sf[HID * 2], sg[HID * HID];

    if (tid < 32) {
        float v = hz[b * HDIM + n * 32 + tid];
        if (tid & 1) sz[tid >> 1] = v;
        else         sh[tid >> 1] = v;
    }
    __syncthreads();

    {
        float acc = bg[tid];
#pragma unroll
        for (int l = 0; l < HID; l++) acc += sz[l] * Wg[l * 256 + tid];
        sg[tid] = tanhf(acc);
    }
    if (tid < 32) {
        float acc = bf[tid];
#pragma unroll
        for (int i = 0; i < HID; i++) acc += sh[i] * Wf[i * 32 + tid];
        sf[tid] = tanhf(acc);
    }
    __syncthreads();

    if (tid < 32) {
        const int i = tid >> 1, c = tid & 1;
        float acc = 0.f;
#pragma unroll
        for (int j = 0; j < HID; j++) acc += sg[i * HID + j] * sf[j * 2 + c];
        const int base = X_DIM + n * 64 + i * 4 + c * 2;
        inpT[(size_t)base * BATCH + b]       = sf[i * 2 + c];
        inpT[(size_t)(base + 1) * BATCH + b] = acc;
    }
    if (tid < HID) {
        float v = sv_t[(b * NODE + n) * 2 + 1];
        inpT[(size_t)(tid * NODE + n) * BATCH + b] = conv_w[tid] * v;
    }
}

// ---------------------------------------------------------------------------
// Kernel B: pre = inp @ W_ih^T + b_ih (Wih streamed evict-first)
// ---------------------------------------------------------------------------
__global__ __launch_bounds__(256) void kB(
    const float* __restrict__ inpT, const float* __restrict__ Wih,
    const float* __restrict__ bih, float* __restrict__ pre)
{
    const int tid = threadIdx.x;
    const int b  = tid & 63;
    const int jg = tid >> 6;
    const int o0 = blockIdx.x * 16 + jg * 4;

    const float* w0 = Wih + (size_t)o0 * IN_DIM;

    float acc[4];
#pragma unroll
    for (int k = 0; k < 4; k++) acc[k] = 0.f;

    for (int i = 0; i < IN_DIM; i += 4) {
        const float x0 = inpT[(size_t)(i    ) * BATCH + b];
        const float x1 = inpT[(size_t)(i + 1) * BATCH + b];
        const float x2 = inpT[(size_t)(i + 2) * BATCH + b];
        const float x3 = inpT[(size_t)(i + 3) * BATCH + b];
#pragma unroll
        for (int k = 0; k < 4; k++) {
            const float4 w = __ldcs(reinterpret_cast<const float4*>(
                                        w0 + (size_t)k * IN_DIM + i));
            acc[k] += w.x * x0 + w.y * x1 + w.z * x2 + w.w * x3;
        }
    }
#pragma unroll
    for (int k = 0; k < 4; k++)
        pre[b * HDIM + o0 + k] = acc[k] + bih[o0 + k];
}

// ---------------------------------------------------------------------------
// Portable signed-int8 lane extraction (aarch64 'char' is unsigned!):
// byte b of word v, sign-extended via shifts.
// ---------------------------------------------------------------------------
__device__ __forceinline__ float sx8(unsigned v, int b)
{
    return (float)((int)(v << (24 - 8 * b)) >> 24);
}

// hi (8 halfs) and lo (8 int8) contribution for one 8-elem group
__device__ __forceinline__ void grp(float& ahi, float& alo,
                                    const uint4& hv, const uint2& lv,
                                    const float4& h0, const float4& h1)
{
    const __half2* ph = reinterpret_cast<const __half2*>(&hv);
    float2 f;
    f = __half22float2(ph[0]); ahi += f.x * h0.x + f.y * h0.y;
    f = __half22float2(ph[1]); ahi += f.x * h0.z + f.y * h0.w;
    f = __half22float2(ph[2]); ahi += f.x * h1.x + f.y * h1.y;
    f = __half22float2(ph[3]); ahi += f.x * h1.z + f.y * h1.w;

    const unsigned a = lv.x, b = lv.y;
    alo += sx8(a, 0) * h0.x + sx8(a, 1) * h0.y + sx8(a, 2) * h0.z + sx8(a, 3) * h0.w
         + sx8(b, 0) * h1.x + sx8(b, 1) * h1.y + sx8(b, 2) * h1.z + sx8(b, 3) * h1.w;
}

// ---------------------------------------------------------------------------
// Kernel C (persistent): smem fp32 tier + streamed fp16hi/int8lo tier.
// 138 blocks x 512 threads, 1 CTA/SM. 48 rows/block, 3 rows/warp.
// Per step DRAM: 6624 rows * 5632 * 3B = 112 MB (hi+lo, evict-first).
// ---------------------------------------------------------------------------
extern __shared__ float s_dyn[];

__global__ __launch_bounds__(512, 1) void kC_persist(
    const float* __restrict__ Wfull, const __half* __restrict__ Whi,
    const int8_t* __restrict__ Wlo, const float* __restrict__ Wsc,
    const float* __restrict__ pre, const float* __restrict__ bhh,
    float* __restrict__ hz, int t)
{
    float* sh = s_dyn;                 // [0, WSTRIDE) floats
    float* wc = s_dyn + WSTRIDE;       // 48 rows * 1024 floats (fp32 cache)
    const int tid  = threadIdx.x;
    const int warp = tid >> 5;
    const int lane = tid & 31;
    const int rbase = blockIdx.x * ROWS_PB + warp * 3;

    const float4* H4 = reinterpret_cast<const float4*>(sh);
    const uint4* HI0 = reinterpret_cast<const uint4*>(Whi + (size_t)(rbase    ) * SELEMS);
    const uint4* HI1 = reinterpret_cast<const uint4*>(Whi + (size_t)(rbase + 1) * SELEMS);
    const uint4* HI2 = reinterpret_cast<const uint4*>(Whi + (size_t)(rbase + 2) * SELEMS);
    const uint2* LO0 = reinterpret_cast<const uint2*>(Wlo + (size_t)(rbase    ) * SELEMS);
    const uint2* LO1 = reinterpret_cast<const uint2*>(Wlo + (size_t)(rbase + 1) * SELEMS);
    const uint2* LO2 = reinterpret_cast<const uint2*>(Wlo + (size_t)(rbase + 2) * SELEMS);
    const float4* C0 = reinterpret_cast<const float4*>(wc + (size_t)(warp * 3    ) * 1024);
    const float4* C1 = reinterpret_cast<const float4*>(wc + (size_t)(warp * 3 + 1) * 1024);
    const float4* C2 = reinterpret_cast<const float4*>(wc + (size_t)(warp * 3 + 2) * 1024);

    const float s0 = Wsc[rbase], s1 = Wsc[rbase + 1], s2 = Wsc[rbase + 2];

    // fill fp32 smem cache (cols [0,1024)) from the original W once per launch
#pragma unroll
    for (int r = 0; r < 3; r++) {
        const float4* src = reinterpret_cast<const float4*>(
            Wfull + (size_t)(rbase + r) * HDIM);
        float4* dst = reinterpret_cast<float4*>(wc + (size_t)(warp * 3 + r) * 1024);
        for (int k = lane; k < 256; k += 32) dst[k] = src[k];
    }
    if (tid < WSTRIDE - HDIM) sh[HDIM + tid] = 0.f;   // zero smem h pad
    __syncthreads();

    for (int step = 0; step < BATCH; step++) {
        float hi0 = 0.f, hi1 = 0.f, hi2 = 0.f;
        float lo0 = 0.f, lo1 = 0.f, lo2 = 0.f;
        float sm0 = 0.f, sm1 = 0.f, sm2 = 0.f;

        if (step > 0) {
            const float* hp = hz + (size_t)(step - 1) * HDIM;
            for (int i = tid; i < HDIM; i += 512) sh[i] = __ldcg(hp + i);
            __syncthreads();

            // streamed tier: 22 iters, x2 unroll; group g covers elems 1024+8g
#pragma unroll 1
            for (int it = 0; it < SITERS; it += 2) {
                uint4 hA[2][3]; uint2 lA[2][3];
                float4 h0[2], h1[2];
#pragma unroll
                for (int j = 0; j < 2; j++) {
                    const int g = (it + j) * 32 + lane;
                    hA[j][0] = __ldcs(&HI0[g]);
                    lA[j][0] = __ldcs(&LO0[g]);
                    hA[j][1] = __ldcs(&HI1[g]);
                    lA[j][1] = __ldcs(&LO1[g]);
                    hA[j][2] = __ldcs(&HI2[g]);
                    lA[j][2] = __ldcs(&LO2[g]);
                }
#pragma unroll
                for (int j = 0; j < 2; j++) {
                    const int g = (it + j) * 32 + lane;
                    h0[j] = H4[256 + 2 * g];
                    h1[j] = H4[256 + 2 * g + 1];
                }
#pragma unroll
                for (int j = 0; j < 2; j++) {
                    grp(hi0, lo0, hA[j][0], lA[j][0], h0[j], h1[j]);
                    grp(hi1, lo1, hA[j][1], lA[j][1], h0[j], h1[j]);
                    grp(hi2, lo2, hA[j][2], lA[j][2], h0[j], h1[j]);
                }
            }
            // smem fp32 tier: f4 [0,256)
#pragma unroll 1
            for (int c = 0; c < 8; c++) {
                const int k = c * 32 + lane;
                const float4 wa = C0[k];
                const float4 wb = C1[k];
                const float4 wcc = C2[k];
                const float4 h  = H4[k];
                sm0 += wa.x*h.x + wa.y*h.y + wa.z*h.z + wa.w*h.w;
                sm1 += wb.x*h.x + wb.y*h.y + wb.z*h.z + wb.w*h.w;
                sm2 += wcc.x*h.x + wcc.y*h.y + wcc.z*h.z + wcc.w*h.w;
            }
        }

        float a0 = sm0 + hi0 + s0 * lo0;
        float a1 = sm1 + hi1 + s1 * lo1;
        float a2 = sm2 + hi2 + s2 * lo2;

#pragma unroll
        for (int s = 16; s; s >>= 1) {
            a0 += __shfl_xor_sync(0xffffffffu, a0, s);
            a1 += __shfl_xor_sync(0xffffffffu, a1, s);
            a2 += __shfl_xor_sync(0xffffffffu, a2, s);
        }
        if (lane == 0) {
            const float* pre_b = pre + (size_t)step * HDIM;
            float* hout = hz + (size_t)step * HDIM;
            __stcg(hout + rbase    , tanhf(a0 + pre_b[rbase    ] + bhh[rbase    ]));
            __stcg(hout + rbase + 1, tanhf(a1 + pre_b[rbase + 1] + bhh[rbase + 1]));
            __stcg(hout + rbase + 2, tanhf(a2 + pre_b[rbase + 2] + bhh[rbase + 2]));
        }

        // grid barrier (also protects smem h WAR for next step's staging)
        __threadfence();
        __syncthreads();
        if (tid == 0) {
            const unsigned k = (unsigned)(t * BATCH + step + 1);
            const unsigned old = atomicAdd(&g_bar[0], 1u);
            if (old == k * NB - 1u) {
                atomicExch(&g_bar[1], k);
            } else {
                volatile unsigned* ph = &g_bar[1];
                while (*ph < k) __nanosleep(64);
            }
        }
        __syncthreads();
    }
}

// ---------------------------------------------------------------------------
extern "C" void kernel_launch(void* const* d_in, const int* in_sizes, int n_in,
                              void* d_out, int out_size)
{
    const float* sv    = (const float*)d_in[0];
    const float* init0 = (const float*)d_in[1];
    const float* Wf    = (const float*)d_in[2];
    const float* bf    = (const float*)d_in[3];
    const float* Wg    = (const float*)d_in[4];
    const float* bg    = (const float*)d_in[5];
    const float* cw    = (const float*)d_in[6];
    const float* Wih   = (const float*)d_in[7];
    const float* bih   = (const float*)d_in[8];
    const float* Whh   = (const float*)d_in[9];
    const float* bhh   = (const float*)d_in[10];

    float *hz, *inpT, *pre, *wsc;
    __half* whi;
    int8_t* wlo;
    unsigned* bar;
    cudaGetSymbolAddress((void**)&hz,   g_hz);
    cudaGetSymbolAddress((void**)&inpT, g_inpT);
    cudaGetSymbolAddress((void**)&pre,  g_pre);
    cudaGetSymbolAddress((void**)&whi,  g_whi);
    cudaGetSymbolAddress((void**)&wlo,  g_wlo);
    cudaGetSymbolAddress((void**)&wsc,  g_wsc);
    cudaGetSymbolAddress((void**)&bar,  g_bar);

    static int smem_set = 0;
    if (!smem_set) {
        cudaFuncSetAttribute(kC_persist,
                             cudaFuncAttributeMaxDynamicSharedMemorySize,
                             SMEM_BYTES);
        smem_set = 1;
    }

    // Launch order: memset, kH, memcpy, kA, kB, kC -> kC is profiled op #5
    cudaMemsetAsync(bar, 0, 2 * sizeof(unsigned));
    kH<<<HDIM, 256>>>(Whh);
    cudaMemcpyAsync(hz, init0, (size_t)BATCH * HDIM * sizeof(float),
                    cudaMemcpyDeviceToDevice);

    for (int t = 0; t < T_STEPS; t++) {
        kA<<<BATCH * NODE, 256>>>(hz, sv + (size_t)t * BATCH * NODE * 2,
                                  Wf, bf, Wg, bg, cw, inpT);
        kB<<<HDIM / 16, 256>>>(inpT, Wih, bih, pre);
        kC_persist<<<NB, 512, SMEM_BYTES>>>(Whh, whi, wlo, wsc, pre, bhh, hz, t);
    }

    cudaMemcpyAsync(d_out, hz, (size_t)BATCH * HDIM * sizeof(float),
                    cudaMemcpyDeviceToDevice);
}

// round 14
// speedup vs baseline: 1.0629x; 1.0629x over previous
#include <cuda_runtime.h>
#include <cuda_fp16.h>
#include <cstdint>

#define T_STEPS 12
#define BATCH   64
#define NODE    207
#define HID     16
#define HDIM    6624          // NODE*HID*2
#define IN_DIM  16560         // NODE*HID*5
#define X_DIM   3312          // NODE*HID
#define WSTRIDE 6656          // padded row length (elems)
#define NB      414           // persistent grid: 414 blocks * 16 rows = 6624
#define ROWS_PB 16
#define GRP     832           // 8-elem groups per row (WSTRIDE/8)
#define GITER   26            // GRP/32 lane-strided iations
// smem: h (WSTRIDE floats) + h8 (WSTRIDE int8 packed as WSTRIDE/4 uint32)
#define SMEM_BYTES (WSTRIDE * 4 + WSTRIDE)   // 33280 B -> 3 CTAs/SM

// Scratch (device globals: allocation-free rule)
__device__ float    g_hz[BATCH * HDIM];
__device__ float    g_inpT[IN_DIM * BATCH];
__device__ float    g_pre[BATCH * HDIM];
__device__ __half   g_whi[(size_t)HDIM * WSTRIDE];  // fp16 hi (88.2 MB, streamed)
__device__ int8_t   g_wlo[(size_t)HDIM * WSTRIDE];  // int8 residual (44.1 MB, streamed)
__device__ float    g_wsc[HDIM];                    // per-row residual scale
__device__ unsigned g_bar[2];                       // [0]=count (monotone), [1]=phase

// ---------------------------------------------------------------------------
// Kernel H: full row: hi = fp16(w); r = w - hi; s = rowmax|r|/127; q = rint(r/s)
// ---------------------------------------------------------------------------
__global__ __launch_bounds__(256) void kH(const float* __restrict__ W)
{
    const int o = blockIdx.x;
    const int tid = threadIdx.x;
    __shared__ float smax[256];

    float m = 0.f;
    for (int i = tid; i < WSTRIDE; i += 256) {
        const float w = (i < HDIM) ? W[(size_t)o * HDIM + i] : 0.f;
        const __half hi = __float2half(w);
        g_whi[(size_t)o * WSTRIDE + i] = hi;
        m = fmaxf(m, fabsf(w - __half2float(hi)));
    }
    smax[tid] = m;
    __syncthreads();
    for (int s = 128; s; s >>= 1) {
        if (tid < s) smax[tid] = fmaxf(smax[tid], smax[tid + s]);
        __syncthreads();
    }
    const float mx = smax[0];
    const float sc = (mx > 0.f) ? (mx / 127.f) : 1.f;
    if (tid == 0) g_wsc[o] = sc;
    const float inv = 1.f / sc;

    for (int i = tid; i < WSTRIDE; i += 256) {
        const float w = (i < HDIM) ? W[(size_t)o * HDIM + i] : 0.f;
        const float r = w - __half2float(__float2half(w));
        float q = rintf(r * inv);
        q = fminf(fmaxf(q, -127.f), 127.f);
        g_wlo[(size_t)o * WSTRIDE + i] = (int8_t)(int)q;
    }
}

// ---------------------------------------------------------------------------
// Kernel A: build inpT[:, b] directly (transposed layout).
// ---------------------------------------------------------------------------
__global__ __launch_bounds__(256) void kA(
    const float* __restrict__ hz, const float* __restrict__ sv_t,
    const float* __restrict__ Wf, const float* __restrict__ bf,
    const float* __restrict__ Wg, const float* __restrict__ bg,
    const float* __restrict__ conv_w, float* __restrict__ inpT)
{
    const int blk = blockIdx.x;
    const int b = blk / NODE;
    const int n = blk % NODE;
    const int tid = threadIdx.x;

    __shared__ float sh[HID], sz[HID], sf[HID * 2], sg[HID * HID];

    if (tid < 32) {
        float v = hz[b * HDIM + n * 32 + tid];
        if (tid & 1) sz[tid >> 1] = v;
        else         sh[tid >> 1] = v;
    }
    __syncthreads();

    {
        float acc = bg[tid];
#pragma unroll
        for (int l = 0; l < HID; l++) acc += sz[l] * Wg[l * 256 + tid];
        sg[tid] = tanhf(acc);
    }
    if (tid < 32) {
        float acc = bf[tid];
#pragma unroll
        for (int i = 0; i < HID; i++) acc += sh[i] * Wf[i * 32 + tid];
        sf[tid] = tanhf(acc);
    }
    __syncthreads();

    if (tid < 32) {
        const int i = tid >> 1, c = tid & 1;
        float acc = 0.f;
#pragma unroll
        for (int j = 0; j < HID; j++) acc += sg[i * HID + j] * sf[j * 2 + c];
        const int base = X_DIM + n * 64 + i * 4 + c * 2;
        inpT[(size_t)base * BATCH + b]       = sf[i * 2 + c];
        inpT[(size_t)(base + 1) * BATCH + b] = acc;
    }
    if (tid < HID) {
        float v = sv_t[(b * NODE + n) * 2 + 1];
        inpT[(size_t)(tid * NODE + n) * BATCH + b] = conv_w[tid] * v;
    }
}

// ---------------------------------------------------------------------------
// Kernel B: pre = inp @ W_ih^T + b_ih (Wih streamed evict-first)
// ---------------------------------------------------------------------------
__global__ __launch_bounds__(256) void kB(
    const float* __restrict__ inpT, const float* __restrict__ Wih,
    const float* __restrict__ bih, float* __restrict__ pre)
{
    const int tid = threadIdx.x;
    const int b  = tid & 63;
    const int jg = tid >> 6;
    const int o0 = blockIdx.x * 16 + jg * 4;

    const float* w0 = Wih + (size_t)o0 * IN_DIM;

    float acc[4];
#pragma unroll
    for (int k = 0; k < 4; k++) acc[k] = 0.f;

    for (int i = 0; i < IN_DIM; i += 4) {
        const float x0 = inpT[(size_t)(i    ) * BATCH + b];
        const float x1 = inpT[(size_t)(i + 1) * BATCH + b];
        const float x2 = inpT[(size_t)(i + 2) * BATCH + b];
        const float x3 = inpT[(size_t)(i + 3) * BATCH + b];
#pragma unroll
        for (int k = 0; k < 4; k++) {
            const float4 w = __ldcs(reinterpret_cast<const float4*>(
                                        w0 + (size_t)k * IN_DIM + i));
            acc[k] += w.x * x0 + w.y * x1 + w.z * x2 + w.w * x3;
        }
    }
#pragma unroll
    for (int k = 0; k < 4; k++)
        pre[b * HDIM + o0 + k] = acc[k] + bih[o0 + k];
}

// ---------------------------------------------------------------------------
// Kernel C (persistent, fp16-hi FFMA + int8-lo DP4A, 3 CTAs/SM):
// 414 blocks x 256 threads (24 warps/SM). 16 rows/block, 2 rows/warp.
// Per step DRAM: 6624 * 6656 * 3B = 132 MB streamed evict-first.
// h staged to smem as fp32 AND quantized int8 (for dp4a residual).
// ---------------------------------------------------------------------------
extern __shared__ float s_dyn[];

__global__ __launch_bounds__(256, 3) void kC_persist(
    const __half* __restrict__ Whi, const int8_t* __restrict__ Wlo,
    const float* __restrict__ Wsc, const float* __restrict__ pre,
    const float* __restrict__ bhh, float* __restrict__ hz, int t)
{
    float*    sh  = s_dyn;                                       // WSTRIDE floats
    unsigned* sh8 = reinterpret_cast<unsigned*>(s_dyn + WSTRIDE);// WSTRIDE/4 words
    const int tid  = threadIdx.x;
    const int warp = tid >> 5;
    const int lane = tid & 31;
    const int rbase = blockIdx.x * ROWS_PB + warp * 2;

    const float4* H4  = reinterpret_cast<const float4*>(sh);
    const uint2*  H8  = reinterpret_cast<const uint2*>(sh8);     // one per 8 elems
    const uint4* HI0 = reinterpret_cast<const uint4*>(Whi + (size_t)(rbase    ) * WSTRIDE);
    const uint4* HI1 = reinterpret_cast<const uint4*>(Whi + (size_t)(rbase + 1) * WSTRIDE);
    const uint2* LO0 = reinterpret_cast<const uint2*>(Wlo + (size_t)(rbase    ) * WSTRIDE);
    const uint2* LO1 = reinterpret_cast<const uint2*>(Wlo + (size_t)(rbase + 1) * WSTRIDE);

    const float fs0 = Wsc[rbase]     * (1.f / 127.f);
    const float fs1 = Wsc[rbase + 1] * (1.f / 127.f);

    for (int step = 0; step < BATCH; step++) {
        const float* pre_b = pre + (size_t)step * HDIM;
        float* hout = hz + (size_t)step * HDIM;

        float a0 = 0.f, a1 = 0.f;

        if (step > 0) {
            __syncthreads();      // WAR vs previous step's smem readers
            // stage h: fp32 float4 + packed int8, 1664 groups-of-4
            const float4* hp4 = reinterpret_cast<const float4*>(
                hz + (size_t)(step - 1) * HDIM);
            for (int i = tid; i < WSTRIDE / 4; i += 256) {
                float4 v;
                if (i < HDIM / 4) v = __ldcg(&hp4[i]);
                else v = make_float4(0.f, 0.f, 0.f, 0.f);
                reinterpret_cast<float4*>(sh)[i] = v;
                const int q0 = (int)rintf(v.x * 127.f);
                const int q1 = (int)rintf(v.y * 127.f);
                const int q2 = (int)rintf(v.z * 127.f);
                const int q3 = (int)rintf(v.w * 127.f);
                sh8[i] = (unsigned)(q0 & 0xff)        | ((unsigned)(q1 & 0xff) << 8)
                       | ((unsigned)(q2 & 0xff) << 16) | ((unsigned)(q3 & 0xff) << 24);
            }
            __syncthreads();

            int i0 = 0, i1 = 0;   // int accumulators for dp4a residual
#pragma unroll 1
            for (int it = 0; it < GITER; it += 2) {
                uint4 hA[2], hB[2];
                uint2 lA[2], lB[2];
                float4 h0[2], h1[2];
                uint2 q8[2];
#pragma unroll
                for (int j = 0; j < 2; j++) {
                    const int g = (it + j) * 32 + lane;
                    hA[j] = __ldcs(&HI0[g]);
                    lA[j] = __ldcs(&LO0[g]);
                    hB[j] = __ldcs(&HI1[g]);
                    lB[j] = __ldcs(&LO1[g]);
                }
#pragma unroll
                for (int j = 0; j < 2; j++) {
                    const int g = (it + j) * 32 + lane;
                    h0[j] = H4[2 * g];
                    h1[j] = H4[2 * g + 1];
                    q8[j] = H8[g];
                }
#pragma unroll
                for (int j = 0; j < 2; j++) {
                    // hi term: fp16 -> fp32 FFMA
                    const __half2* pa = reinterpret_cast<const __half2*>(&hA[j]);
                    const __half2* pb = reinterpret_cast<const __half2*>(&hB[j]);
                    float2 f;
                    f = __half22float2(pa[0]); a0 += f.x*h0[j].x + f.y*h0[j].y;
                    f = __half22float2(pa[1]); a0 += f.x*h0[j].z + f.y*h0[j].w;
                    f = __half22float2(pa[2]); a0 += f.x*h1[j].x + f.y*h1[j].y;
                    f = __half22float2(pa[3]); a0 += f.x*h1[j].z + f.y*h1[j].w;
                    f = __half22float2(pb[0]); a1 += f.x*h0[j].x + f.y*h0[j].y;
                    f = __half22float2(pb[1]); a1 += f.x*h0[j].z + f.y*h0[j].w;
                    f = __half22float2(pb[2]); a1 += f.x*h1[j].x + f.y*h1[j].y;
                    f = __half22float2(pb[3]); a1 += f.x*h1[j].z + f.y*h1[j].w;
                    // lo term: dp4a int8 x int8(h)
                    i0 = __dp4a((int)lA[j].x, (int)q8[j].x, i0);
                    i0 = __dp4a((int)lA[j].y, (int)q8[j].y, i0);
                    i1 = __dp4a((int)lB[j].x, (int)q8[j].x, i1);
                    i1 = __dp4a((int)lB[j].y, (int)q8[j].y, i1);
                }
            }
            a0 += fs0 * (float)i0;
            a1 += fs1 * (float)i1;
        }

#pragma unroll
        for (int s = 16; s; s >>= 1) {
            a0 += __shfl_xor_sync(0xffffffffu, a0, s);
            a1 += __shfl_xor_sync(0xffffffffu, a1, s);
        }
        if (lane == 0) {
            __stcg(hout + rbase    , tanhf(a0 + pre_b[rbase    ] + bhh[rbase    ]));
            __stcg(hout + rbase + 1, tanhf(a1 + pre_b[rbase + 1] + bhh[rbase + 1]));
        }

        // grid barrier
        __threadfence();
        __syncthreads();
        if (tid == 0) {
            const unsigned k = (unsigned)(t * BATCH + step + 1);
            const unsigned old = atomicAdd(&g_bar[0], 1u);
            if (old == k * NB - 1u) {
                atomicExch(&g_bar[1], k);
            } else {
                volatile unsigned* ph = &g_bar[1];
                while (*ph < k) __nanosleep(64);
            }
        }
        __syncthreads();
    }
}

// ---------------------------------------------------------------------------
extern "C" void kernel_launch(void* const* d_in, const int* in_sizes, int n_in,
                              void* d_out, int out_size)
{
    const float* sv    = (const float*)d_in[0];
    const float* init0 = (const float*)d_in[1];
    const float* Wf    = (const float*)d_in[2];
    const float* bf    = (const float*)d_in[3];
    const float* Wg    = (const float*)d_in[4];
    const float* bg    = (const float*)d_in[5];
    const float* cw    = (const float*)d_in[6];
    const float* Wih   = (const float*)d_in[7];
    const float* bih   = (const float*)d_in[8];
    const float* Whh   = (const float*)d_in[9];
    const float* bhh   = (const float*)d_in[10];

    float *hz, *inpT, *pre, *wsc;
    __half* whi;
    int8_t* wlo;
    unsigned* bar;
    cudaGetSymbolAddress((void**)&hz,   g_hz);
    cudaGetSymbolAddress((void**)&inpT, g_inpT);
    cudaGetSymbolAddress((void**)&pre,  g_pre);
    cudaGetSymbolAddress((void**)&whi,  g_whi);
    cudaGetSymbolAddress((void**)&wlo,  g_wlo);
    cudaGetSymbolAddress((void**)&wsc,  g_wsc);
    cudaGetSymbolAddress((void**)&bar,  g_bar);

    static int smem_set = 0;
    if (!smem_set) {
        cudaFuncSetAttribute(kC_persist,
                             cudaFuncAttributeMaxDynamicSharedMemorySize,
                             SMEM_BYTES);
        smem_set = 1;
    }

    // Launch order: memset, kH, memcpy, kA, kB, kC -> kC is profiled op #5
    cudaMemsetAsync(bar, 0, 2 * sizeof(unsigned));
    kH<<<HDIM, 256>>>(Whh);
    cudaMemcpyAsync(hz, init0, (size_t)BATCH * HDIM * sizeof(float),
                    cudaMemcpyDeviceToDevice);

    for (int t = 0; t < T_STEPS; t++) {
        kA<<<BATCH * NODE, 256>>>(hz, sv + (size_t)t * BATCH * NODE * 2,
                                  Wf, bf, Wg, bg, cw, inpT);
        kB<<<HDIM / 16, 256>>>(inpT, Wih, bih, pre);
        kC_persist<<<NB, 256, SMEM_BYTES>>>(whi, wlo, wsc, pre, bhh, hz, t);
    }

    cudaMemcpyAsync(d_out, hz, (size_t)BATCH * HDIM * sizeof(float),
                    cudaMemcpyDeviceToDevice);
}